// round 16
// baseline (speedup 1.0000x reference)
#include <cuda_runtime.h>
#include <math.h>

// ---------------- problem constants (static) ----------------
#define NN   32768
#define EE   524288
#define BB   32
#define NPG  1024
#define KK   512
#define HH   4
#define HIDC 64
#define HD   256
#define INC  128
#define SLOPE 0.2f

// output layout (concatenated float32)
#define OFF_XP 0u
#define OFF_EI 1048576u
#define OFF_EN 2097152u
#define OFF_BO 6291456u
#define OFF_X1 6307840u

// ---------------- device scratch ----------------
__device__ float g_h[NN * HD];
__device__ float g_xg[NN * HD];
__device__ float g_xl[NN * HIDC];
__device__ float g_alsrc[NN * HH];
__device__ float g_aldst[NN * HH];
__device__ float g_m[NN * HH];
__device__ float g_den[NN * HH];
__device__ int   g_deg[NN];
__device__ int   g_rs[NN + 1];
__device__ int   g_cur[NN];
__device__ int   g_eid[EE];           // edge id per CSR slot (sorted ascending)
__device__ float g_ex[EE * HH];       // exp term per CSR slot/head
__device__ float g_sex[NN * HH];      // self-loop exp term
__device__ float g_score[NN];
__device__ int   g_perm[BB * KK];
__device__ float g_topv[BB * KK];
__device__ int   g_nmap[NN];

// ---------------- helpers ----------------
__device__ __forceinline__ float lrelu(float x) { return x > 0.f ? x : __fmul_rn(SLOPE, x); }

__device__ __forceinline__ void atomicMaxF(float* addr, float v) {
    if (v >= 0.f) atomicMax((int*)addr, __float_as_int(v));
    else          atomicMin((unsigned int*)addr, __float_as_uint(v));
}

// ---------------- kernels ----------------
__global__ void init_kernel() {
    int i = blockIdx.x * blockDim.x + threadIdx.x;
    if (i < NN) { g_deg[i] = 0; g_nmap[i] = -1; }
}

// Tiled SGEMM: C = A*Bm (+bias). Sequential-k FMA per output element.
__global__ void gemm_kernel(const float* __restrict__ A, const float* __restrict__ Bm,
                            const float* __restrict__ bias, float* __restrict__ C,
                            int Kdim, int Ncols) {
    __shared__ float As[64][16];
    __shared__ float Bs[16][64];
    int t  = threadIdx.x;
    int tx = t & 15, ty = t >> 4;
    int row0 = blockIdx.y * 64, col0 = blockIdx.x * 64;
    float acc[4][4] = {};
    for (int k0 = 0; k0 < Kdim; k0 += 16) {
        {
            int r = t >> 2, kk4 = (t & 3) << 2;
            *(float4*)(&As[r][kk4]) =
                *(const float4*)(A + (size_t)(row0 + r) * Kdim + k0 + kk4);
        }
        {
            int kk = t >> 4, c4 = (t & 15) << 2;
            *(float4*)(&Bs[kk][c4]) =
                *(const float4*)(Bm + (size_t)(k0 + kk) * Ncols + col0 + c4);
        }
        __syncthreads();
#pragma unroll
        for (int kk = 0; kk < 16; kk++) {
            float a[4], b[4];
#pragma unroll
            for (int i = 0; i < 4; i++) a[i] = As[ty * 4 + i][kk];
            float4 bv = *(float4*)(&Bs[kk][tx * 4]);
            b[0] = bv.x; b[1] = bv.y; b[2] = bv.z; b[3] = bv.w;
#pragma unroll
            for (int i = 0; i < 4; i++)
#pragma unroll
                for (int j = 0; j < 4; j++) acc[i][j] = __fmaf_rn(a[i], b[j], acc[i][j]);
        }
        __syncthreads();
    }
#pragma unroll
    for (int i = 0; i < 4; i++) {
        int r = row0 + ty * 4 + i;
        int c = col0 + tx * 4;
        float4 o;
        o.x = acc[i][0]; o.y = acc[i][1]; o.z = acc[i][2]; o.w = acc[i][3];
        if (bias) {
            o.x = __fadd_rn(o.x, bias[c + 0]);
            o.y = __fadd_rn(o.y, bias[c + 1]);
            o.z = __fadd_rn(o.z, bias[c + 2]);
            o.w = __fadd_rn(o.w, bias[c + 3]);
        }
        *(float4*)(&C[(size_t)r * Ncols + c]) = o;
    }
}

// al_src/al_dst: XLA:GPU row-reduce vec2 form — warp per (node,head),
// lane l accumulates ADJACENT elements 2l, 2l+1 (mul, add-of-mul), shfl tree.
__global__ void al_kernel(const float* __restrict__ asrc, const float* __restrict__ adst) {
    int w = (blockIdx.x * blockDim.x + threadIdx.x) >> 5;   // (node,head)
    int lane = threadIdx.x & 31;
    if (w >= NN * HH) return;
    int n = w >> 2, head = w & 3;
    const float* hrow = g_h + (size_t)n * HD + head * HIDC;
    const float* ar = asrc + head * HIDC;
    const float* dr = adst + head * HIDC;
    int c = lane * 2;
    float s = __fmul_rn(hrow[c], ar[c]);
    s = __fadd_rn(s, __fmul_rn(hrow[c + 1], ar[c + 1]));
    float d = __fmul_rn(hrow[c], dr[c]);
    d = __fadd_rn(d, __fmul_rn(hrow[c + 1], dr[c + 1]));
#pragma unroll
    for (int off = 16; off > 0; off >>= 1) {
        s = __fadd_rn(s, __shfl_down_sync(0xffffffffu, s, off));
        d = __fadd_rn(d, __shfl_down_sync(0xffffffffu, d, off));
    }
    if (lane == 0) { g_alsrc[w] = s; g_aldst[w] = d; }
}

__global__ void minit_kernel() {
    int i = blockIdx.x * blockDim.x + threadIdx.x;
    if (i < NN * HH) g_m[i] = lrelu(__fadd_rn(g_alsrc[i], g_aldst[i]));
}

__global__ void edge_max_kernel(const int* __restrict__ ei) {
    int e = blockIdx.x * blockDim.x + threadIdx.x;
    if (e >= EE) return;
    int s = ei[e], d = ei[EE + e];
    if ((unsigned)s >= NN || (unsigned)d >= NN) return;
    atomicAdd(&g_deg[d], 1);
#pragma unroll
    for (int h = 0; h < HH; h++)
        atomicMaxF(&g_m[d * HH + h], lrelu(__fadd_rn(g_alsrc[s * HH + h], g_aldst[d * HH + h])));
}

__global__ void scan_kernel() {
    __shared__ int s[1024];
    int t = threadIdx.x;
    int base = t * 32;
    int local[32];
    int acc = 0;
#pragma unroll
    for (int i = 0; i < 32; i++) { local[i] = acc; acc += g_deg[base + i]; }
    s[t] = acc;
    __syncthreads();
    for (int off = 1; off < 1024; off <<= 1) {
        int v = (t >= off) ? s[t - off] : 0;
        __syncthreads();
        s[t] += v;
        __syncthreads();
    }
    int offbase = (t == 0) ? 0 : s[t - 1];
#pragma unroll
    for (int i = 0; i < 32; i++) {
        int rs = offbase + local[i];
        g_rs[base + i] = rs;
        g_cur[base + i] = rs;
    }
    if (t == 1023) g_rs[NN] = s[1023];
}

__global__ void scatter_kernel(const int* __restrict__ ei) {
    int e = blockIdx.x * blockDim.x + threadIdx.x;
    if (e >= EE) return;
    int d = ei[EE + e];
    if ((unsigned)ei[e] >= NN || (unsigned)d >= NN) return;
    int p = atomicAdd(&g_cur[d], 1);
    g_eid[p] = e;
}

__global__ void sortcsr_kernel() {
    int n = blockIdx.x * blockDim.x + threadIdx.x;
    if (n >= NN) return;
    int beg = g_rs[n], end = g_rs[n + 1];
    for (int i = beg + 1; i < end; i++) {
        int v = g_eid[i], j = i - 1;
        while (j >= beg && g_eid[j] > v) { g_eid[j + 1] = g_eid[j]; j--; }
        g_eid[j + 1] = v;
    }
}

// denominators + cached exp terms: ASCENDING edge order, self-loop LAST (libdevice expf)
__global__ void den_kernel(const int* __restrict__ ei) {
    int idx = blockIdx.x * blockDim.x + threadIdx.x;
    if (idx >= NN * HH) return;
    int n = idx >> 2, head = idx & 3;
    float m  = g_m[idx];
    float ad = g_aldst[idx];
    float acc = 0.f;
    int beg = g_rs[n], end = g_rs[n + 1];
    for (int i = beg; i < end; i++) {
        int s = ei[g_eid[i]];
        float v = lrelu(__fadd_rn(g_alsrc[s * HH + head], ad));
        float ex = expf(__fsub_rn(v, m));
        g_ex[(size_t)i * HH + head] = ex;
        acc = __fadd_rn(acc, ex);
    }
    float vs = lrelu(__fadd_rn(g_alsrc[idx], ad));
    float exs = expf(__fsub_rn(vs, m));
    g_sex[idx] = exs;
    acc = __fadd_rn(acc, exs);
    g_den[idx] = acc;
}

// aggregation: warp per node, lane owns 8 channels; ASCENDING edge order, self LAST.
__global__ void agg_kernel(const int* __restrict__ ei, const float* __restrict__ bgat) {
    int n = (blockIdx.x * blockDim.x + threadIdx.x) >> 5;
    int lane = threadIdx.x & 31;
    if (n >= NN) return;
    int head = lane >> 3;
    int c0 = lane * 8;
    float den = g_den[n * HH + head];
    float acc[8] = {};
    int beg = g_rs[n], end = g_rs[n + 1];
    for (int i = beg; i < end; i++) {
        int s = ei[g_eid[i]];
        float a = __fdiv_rn(g_ex[(size_t)i * HH + head], den);
        const float4* hr = (const float4*)(g_h + (size_t)s * HD + c0);
        float4 h0 = hr[0], h1 = hr[1];
        acc[0] = __fadd_rn(acc[0], __fmul_rn(a, h0.x));
        acc[1] = __fadd_rn(acc[1], __fmul_rn(a, h0.y));
        acc[2] = __fadd_rn(acc[2], __fmul_rn(a, h0.z));
        acc[3] = __fadd_rn(acc[3], __fmul_rn(a, h0.w));
        acc[4] = __fadd_rn(acc[4], __fmul_rn(a, h1.x));
        acc[5] = __fadd_rn(acc[5], __fmul_rn(a, h1.y));
        acc[6] = __fadd_rn(acc[6], __fmul_rn(a, h1.z));
        acc[7] = __fadd_rn(acc[7], __fmul_rn(a, h1.w));
    }
    {
        float a = __fdiv_rn(g_sex[n * HH + head], den);
        const float4* hr = (const float4*)(g_h + (size_t)n * HD + c0);
        float4 h0 = hr[0], h1 = hr[1];
        acc[0] = __fadd_rn(acc[0], __fmul_rn(a, h0.x));
        acc[1] = __fadd_rn(acc[1], __fmul_rn(a, h0.y));
        acc[2] = __fadd_rn(acc[2], __fmul_rn(a, h0.z));
        acc[3] = __fadd_rn(acc[3], __fmul_rn(a, h0.w));
        acc[4] = __fadd_rn(acc[4], __fmul_rn(a, h1.x));
        acc[5] = __fadd_rn(acc[5], __fmul_rn(a, h1.y));
        acc[6] = __fadd_rn(acc[6], __fmul_rn(a, h1.z));
        acc[7] = __fadd_rn(acc[7], __fmul_rn(a, h1.w));
    }
    float4 o0, o1;
    o0.x = __fadd_rn(acc[0], bgat[c0 + 0]);
    o0.y = __fadd_rn(acc[1], bgat[c0 + 1]);
    o0.z = __fadd_rn(acc[2], bgat[c0 + 2]);
    o0.w = __fadd_rn(acc[3], bgat[c0 + 3]);
    o1.x = __fadd_rn(acc[4], bgat[c0 + 4]);
    o1.y = __fadd_rn(acc[5], bgat[c0 + 5]);
    o1.z = __fadd_rn(acc[6], bgat[c0 + 6]);
    o1.w = __fadd_rn(acc[7], bgat[c0 + 7]);
    float4* op = (float4*)(g_xg + (size_t)n * HD + c0);
    op[0] = o0; op[1] = o1;
}

// score: XLA:GPU row-reduce vec2 — warp per node, lane l: elements 2l, 2l+1
// (mul, add-of-mul), shfl-down tree; div.rn; tanhf.
__global__ void score_kernel(const float* __restrict__ p) {
    int n = (blockIdx.x * blockDim.x + threadIdx.x) >> 5;
    int lane = threadIdx.x & 31;
    if (n >= NN) return;
    const float* xr = g_xl + (size_t)n * HIDC;
    int c = lane * 2;
    float z = __fmul_rn(xr[c], p[c]);
    z = __fadd_rn(z, __fmul_rn(xr[c + 1], p[c + 1]));
    float q = __fmul_rn(p[c], p[c]);
    q = __fadd_rn(q, __fmul_rn(p[c + 1], p[c + 1]));
#pragma unroll
    for (int off = 16; off > 0; off >>= 1) {
        z = __fadd_rn(z, __shfl_down_sync(0xffffffffu, z, off));
        q = __fadd_rn(q, __shfl_down_sync(0xffffffffu, q, off));
    }
    if (lane == 0) g_score[n] = tanhf(__fdiv_rn(z, sqrtf(q)));
}

// per-graph bitonic sort of 1024 (score desc, index asc); take top 512
__global__ void topk_kernel() {
    __shared__ float sv[1024];
    __shared__ int   si[1024];
    int b = blockIdx.x, t = threadIdx.x;
    sv[t] = g_score[b * NPG + t];
    si[t] = t;
    __syncthreads();
    for (int k = 2; k <= 1024; k <<= 1) {
        for (int j = k >> 1; j > 0; j >>= 1) {
            int ixj = t ^ j;
            if (ixj > t) {
                float v1 = sv[t], v2 = sv[ixj];
                int   i1 = si[t], i2 = si[ixj];
                bool before = (v1 > v2) || (v1 == v2 && i1 < i2);
                bool keep = ((t & k) == 0) ? before : !before;
                if (!keep) { sv[t] = v2; sv[ixj] = v1; si[t] = i2; si[ixj] = i1; }
            }
            __syncthreads();
        }
    }
    if (t < KK) {
        int gi = b * NPG + si[t];
        g_perm[b * KK + t] = gi;
        g_topv[b * KK + t] = sv[t];
        g_nmap[gi] = b * KK + t;
    }
}

__global__ void xp_kernel(float* __restrict__ out) {
    int idx = blockIdx.x * blockDim.x + threadIdx.x;
    if (idx >= BB * KK * HIDC) return;
    int r = idx >> 6, c = idx & 63;
    int node = g_perm[r];
    out[OFF_XP + idx] = __fmul_rn(g_xl[(size_t)node * HIDC + c], g_topv[r]);
    if (c == 0) out[OFF_BO + r] = (float)(r >> 9);
}

__global__ void edgeout_kernel(const int* __restrict__ ei,
                               const float* __restrict__ edge, float* __restrict__ out) {
    int e = blockIdx.x * blockDim.x + threadIdx.x;
    if (e >= EE) return;
    int s = ei[e], d = ei[EE + e];
    bool inb = ((unsigned)s < NN) && ((unsigned)d < NN);
    int ns = inb ? g_nmap[s] : -1;
    int nd = inb ? g_nmap[d] : -1;
    bool val = (ns >= 0) && (nd >= 0);
    out[OFF_EI + e]      = val ? (float)ns : -1.0f;
    out[OFF_EI + EE + e] = val ? (float)nd : -1.0f;
    const float4* ep = (const float4*)(edge + (size_t)e * 8);
    float4 a = ep[0], b2 = ep[1];
    if (!val) { a = make_float4(0.f, 0.f, 0.f, 0.f); b2 = a; }
    float4* op = (float4*)(out + OFF_EN + (size_t)e * 8);
    op[0] = a; op[1] = b2;
}

// x1: thread per (graph, channel); sequential r, div.rn for mean
__global__ void x1_kernel(float* __restrict__ out) {
    int idx = blockIdx.x * blockDim.x + threadIdx.x;   // BB*HIDC
    if (idx >= BB * HIDC) return;
    int b = idx >> 6, c = idx & 63;
    const float* xp = out + OFF_XP + (size_t)b * KK * HIDC;
    float sum = 0.f, mx = -INFINITY;
    for (int r = 0; r < KK; r++) {
        float v = xp[(size_t)r * HIDC + c];
        sum = __fadd_rn(sum, v);
        mx = fmaxf(mx, v);
    }
    out[OFF_X1 + b * 128 + c]      = __fdiv_rn(sum, 512.0f);
    out[OFF_X1 + b * 128 + 64 + c] = mx;
}

// ---------------- launcher ----------------
extern "C" void kernel_launch(void* const* d_in, const int* in_sizes, int n_in,
                              void* d_out, int out_size) {
    const float* x     = (const float*)d_in[0];
    const int*   ei    = (const int*)d_in[1];
    const float* edge  = (const float*)d_in[2];
    const float* W     = (const float*)d_in[4];
    const float* a_src = (const float*)d_in[5];
    const float* a_dst = (const float*)d_in[6];
    const float* b_gat = (const float*)d_in[7];
    const float* W_lin = (const float*)d_in[8];
    const float* b_lin = (const float*)d_in[9];
    const float* p_pool= (const float*)d_in[10];
    float* out = (float*)d_out;

    float *p_h = nullptr, *p_xg = nullptr, *p_xl = nullptr;
    cudaGetSymbolAddress((void**)&p_h,  g_h);
    cudaGetSymbolAddress((void**)&p_xg, g_xg);
    cudaGetSymbolAddress((void**)&p_xl, g_xl);

    init_kernel<<<NN / 256, 256>>>();

    dim3 g1(HD / 64, NN / 64);
    gemm_kernel<<<g1, 256>>>(x, W, nullptr, p_h, INC, HD);

    al_kernel<<<NN * HH * 32 / 256, 256>>>(a_src, a_dst);
    minit_kernel<<<NN * HH / 256, 256>>>();
    edge_max_kernel<<<EE / 256, 256>>>(ei);
    scan_kernel<<<1, 1024>>>();
    scatter_kernel<<<EE / 256, 256>>>(ei);
    sortcsr_kernel<<<NN / 256, 256>>>();
    den_kernel<<<NN * HH / 256, 256>>>(ei);
    agg_kernel<<<NN * 32 / 256, 256>>>(ei, b_gat);

    dim3 g2(HIDC / 64, NN / 64);
    gemm_kernel<<<g2, 256>>>(p_xg, W_lin, b_lin, p_xl, HD, HIDC);

    score_kernel<<<NN * 32 / 256, 256>>>(p_pool);
    topk_kernel<<<BB, 1024>>>();
    xp_kernel<<<BB * KK * HIDC / 256, 256>>>(out);
    edgeout_kernel<<<EE / 256, 256>>>(ei, edge, out);
    x1_kernel<<<BB * HIDC / 256, 256>>>(out);
}

// round 17
// speedup vs baseline: 1.0260x; 1.0260x over previous
#include <cuda_runtime.h>
#include <math.h>

// ---------------- problem constants (static) ----------------
#define NN   32768
#define EE   524288
#define BB   32
#define NPG  1024
#define KK   512
#define HH   4
#define HIDC 64
#define HD   256
#define INC  128
#define SLOPE 0.2f

// output layout (concatenated float32)
#define OFF_XP 0u
#define OFF_EI 1048576u
#define OFF_EN 2097152u
#define OFF_BO 6291456u
#define OFF_X1 6307840u

// ---------------- device scratch ----------------
__device__ float g_h[NN * HD];
__device__ float g_xg[NN * HD];
__device__ float g_xl[NN * HIDC];
__device__ float g_alsrc[NN * HH];
__device__ float g_aldst[NN * HH];
__device__ float g_m[NN * HH];
__device__ int   g_deg[NN];
__device__ int   g_rs[NN + 1];
__device__ int   g_cur[NN];
__device__ int   g_eid[EE];           // edge id per CSR slot (sorted ascending)
__device__ int   g_csrc[EE];          // src per CSR slot (post-sort)
__device__ float g_score[NN];
__device__ int   g_perm[BB * KK];
__device__ float g_topv[BB * KK];
__device__ int   g_nmap[NN];

// ---------------- helpers ----------------
__device__ __forceinline__ float lrelu(float x) { return x > 0.f ? x : __fmul_rn(SLOPE, x); }

__device__ __forceinline__ void atomicMaxF(float* addr, float v) {
    if (v >= 0.f) atomicMax((int*)addr, __float_as_int(v));
    else          atomicMin((unsigned int*)addr, __float_as_uint(v));
}

// ---------------- kernels ----------------
__global__ void init_kernel() {
    int i = blockIdx.x * blockDim.x + threadIdx.x;
    if (i < NN) { g_deg[i] = 0; g_nmap[i] = -1; }
}

// Tiled SGEMM: C = A*Bm (+bias). Double-buffered, 8xTN micro-tile.
// Bit-exact: each output accumulates sequential ascending-k FMA, bias add.rn.
template<int BM, int BN, int TM, int TN>
__global__ void __launch_bounds__(256) gemm_tiled(
    const float* __restrict__ A, const float* __restrict__ Bm,
    const float* __restrict__ bias, float* __restrict__ C,
    int Kdim, int Ncols) {
    constexpr int BK = 16;
    constexpr int PAD = 4;
    constexpr int NTX = BN / TN;                 // threads along N (16)
    constexpr int NA = (BM * BK / 4) / 256;      // float4 A-loads per thread
    constexpr int NB = (BN * BK / 4) / 256;      // float4 B-loads per thread
    __shared__ float As[2][BK][BM + PAD];
    __shared__ float Bs[2][BK][BN];
    int t = threadIdx.x;
    int tx = t % NTX, ty = t / NTX;
    int row0 = blockIdx.y * BM, col0 = blockIdx.x * BN;

    float4 ra[NA], rb[NB];
    float acc[TM][TN] = {};
    int nk = Kdim / BK;

#define LOAD_A(kt)                                                            \
    _Pragma("unroll") for (int i = 0; i < NA; i++) {                          \
        int f = t + i * 256; int m = f >> 2, kq = (f & 3) << 2;               \
        ra[i] = *(const float4*)(A + (size_t)(row0 + m) * Kdim + (kt) * BK + kq); }
#define LOAD_B(kt)                                                            \
    _Pragma("unroll") for (int i = 0; i < NB; i++) {                          \
        int g = t + i * 256; int kk = g / (BN / 4), n4 = (g % (BN / 4)) << 2; \
        rb[i] = *(const float4*)(Bm + (size_t)((kt) * BK + kk) * Ncols + col0 + n4); }
#define STORE_AB(buf)                                                         \
    _Pragma("unroll") for (int i = 0; i < NA; i++) {                          \
        int f = t + i * 256; int m = f >> 2, kq = (f & 3) << 2;               \
        As[buf][kq + 0][m] = ra[i].x; As[buf][kq + 1][m] = ra[i].y;           \
        As[buf][kq + 2][m] = ra[i].z; As[buf][kq + 3][m] = ra[i].w; }         \
    _Pragma("unroll") for (int i = 0; i < NB; i++) {                          \
        int g = t + i * 256; int kk = g / (BN / 4), n4 = (g % (BN / 4)) << 2; \
        *(float4*)(&Bs[buf][kk][n4]) = rb[i]; }

    LOAD_A(0); LOAD_B(0);
    STORE_AB(0);
    __syncthreads();
    for (int kt = 0; kt < nk; kt++) {
        int buf = kt & 1;
        if (kt + 1 < nk) { LOAD_A(kt + 1); LOAD_B(kt + 1); }
#pragma unroll
        for (int kk = 0; kk < BK; kk++) {
            float af[TM], bf[TN];
#pragma unroll
            for (int i = 0; i < TM; i += 4)
                *(float4*)(&af[i]) = *(float4*)(&As[buf][kk][ty * TM + i]);
#pragma unroll
            for (int j = 0; j < TN; j += 4)
                *(float4*)(&bf[j]) = *(float4*)(&Bs[buf][kk][tx * TN + j]);
#pragma unroll
            for (int i = 0; i < TM; i++)
#pragma unroll
                for (int j = 0; j < TN; j++)
                    acc[i][j] = __fmaf_rn(af[i], bf[j], acc[i][j]);
        }
        if (kt + 1 < nk) { STORE_AB(buf ^ 1); }
        __syncthreads();
    }
#pragma unroll
    for (int i = 0; i < TM; i++) {
        int r = row0 + ty * TM + i;
#pragma unroll
        for (int j = 0; j < TN; j += 4) {
            int c = col0 + tx * TN + j;
            float4 o;
            o.x = acc[i][j]; o.y = acc[i][j + 1]; o.z = acc[i][j + 2]; o.w = acc[i][j + 3];
            if (bias) {
                o.x = __fadd_rn(o.x, bias[c + 0]);
                o.y = __fadd_rn(o.y, bias[c + 1]);
                o.z = __fadd_rn(o.z, bias[c + 2]);
                o.w = __fadd_rn(o.w, bias[c + 3]);
            }
            *(float4*)(&C[(size_t)r * Ncols + c]) = o;
        }
    }
#undef LOAD_A
#undef LOAD_B
#undef STORE_AB
}

// al_src/al_dst + m-init: vec2 adjacent-pair lane accumulation + shfl tree.
__global__ void al_kernel(const float* __restrict__ asrc, const float* __restrict__ adst) {
    int w = (blockIdx.x * blockDim.x + threadIdx.x) >> 5;   // (node,head)
    int lane = threadIdx.x & 31;
    if (w >= NN * HH) return;
    int n = w >> 2, head = w & 3;
    const float* hrow = g_h + (size_t)n * HD + head * HIDC;
    const float* ar = asrc + head * HIDC;
    const float* dr = adst + head * HIDC;
    int c = lane * 2;
    float s = __fmul_rn(hrow[c], ar[c]);
    s = __fadd_rn(s, __fmul_rn(hrow[c + 1], ar[c + 1]));
    float d = __fmul_rn(hrow[c], dr[c]);
    d = __fadd_rn(d, __fmul_rn(hrow[c + 1], dr[c + 1]));
#pragma unroll
    for (int off = 16; off > 0; off >>= 1) {
        s = __fadd_rn(s, __shfl_down_sync(0xffffffffu, s, off));
        d = __fadd_rn(d, __shfl_down_sync(0xffffffffu, d, off));
    }
    if (lane == 0) {
        g_alsrc[w] = s;
        g_aldst[w] = d;
        g_m[w] = lrelu(__fadd_rn(s, d));   // fused minit (identical expression)
    }
}

__global__ void edge_max_kernel(const int* __restrict__ ei) {
    int e = blockIdx.x * blockDim.x + threadIdx.x;
    if (e >= EE) return;
    int s = ei[e], d = ei[EE + e];
    if ((unsigned)s >= NN || (unsigned)d >= NN) return;
    atomicAdd(&g_deg[d], 1);
#pragma unroll
    for (int h = 0; h < HH; h++)
        atomicMaxF(&g_m[d * HH + h], lrelu(__fadd_rn(g_alsrc[s * HH + h], g_aldst[d * HH + h])));
}

__global__ void scan_kernel() {
    __shared__ int s[1024];
    int t = threadIdx.x;
    int base = t * 32;
    int local[32];
    int acc = 0;
#pragma unroll
    for (int i = 0; i < 32; i++) { local[i] = acc; acc += g_deg[base + i]; }
    s[t] = acc;
    __syncthreads();
    for (int off = 1; off < 1024; off <<= 1) {
        int v = (t >= off) ? s[t - off] : 0;
        __syncthreads();
        s[t] += v;
        __syncthreads();
    }
    int offbase = (t == 0) ? 0 : s[t - 1];
#pragma unroll
    for (int i = 0; i < 32; i++) {
        int rs = offbase + local[i];
        g_rs[base + i] = rs;
        g_cur[base + i] = rs;
    }
    if (t == 1023) g_rs[NN] = s[1023];
}

__global__ void scatter_kernel(const int* __restrict__ ei) {
    int e = blockIdx.x * blockDim.x + threadIdx.x;
    if (e >= EE) return;
    int d = ei[EE + e];
    if ((unsigned)ei[e] >= NN || (unsigned)d >= NN) return;
    int p = atomicAdd(&g_cur[d], 1);
    g_eid[p] = e;
}

// sort each node's slot segment ascending by edge id (local-buffer insertion
// sort, L1-resident), then materialize g_csrc = ei[eid].
__global__ void sortcsr_kernel(const int* __restrict__ ei) {
    int n = blockIdx.x * blockDim.x + threadIdx.x;
    if (n >= NN) return;
    int beg = g_rs[n], end = g_rs[n + 1];
    int cnt = end - beg;
    if (cnt <= 48) {
        int buf[48];
        for (int i = 0; i < cnt; i++) buf[i] = g_eid[beg + i];
        for (int i = 1; i < cnt; i++) {
            int v = buf[i], j = i - 1;
            while (j >= 0 && buf[j] > v) { buf[j + 1] = buf[j]; j--; }
            buf[j + 1] = v;
        }
        for (int i = 0; i < cnt; i++) {
            g_eid[beg + i] = buf[i];
            g_csrc[beg + i] = ei[buf[i]];
        }
    } else {
        for (int i = beg + 1; i < end; i++) {
            int v = g_eid[i], j = i - 1;
            while (j >= beg && g_eid[j] > v) { g_eid[j + 1] = g_eid[j]; j--; }
            g_eid[j + 1] = v;
        }
        for (int i = beg; i < end; i++) g_csrc[i] = ei[g_eid[i]];
    }
}

// Fused softmax-denominator + aggregation: one warp per node.
// Phase A: parallel exp into smem (identical values). Phase B: lanes 0-3 do
// sequential ascending sums per head, self-loop LAST. Phase C: agg, self LAST.
__global__ void softagg_kernel(const float* __restrict__ bgat) {
    __shared__ float exs[8][256];          // per warp: 64 slots x 4 heads
    int wb = threadIdx.x >> 5;
    int n = (blockIdx.x * blockDim.x + threadIdx.x) >> 5;
    int lane = threadIdx.x & 31;
    if (n >= NN) return;
    int beg = g_rs[n], end = g_rs[n + 1];
    int deg = end - beg;
    float* exw = exs[wb];
    bool cached = (deg <= 64);
    if (cached) {
        for (int idx = lane; idx < deg * 4; idx += 32) {
            int i = idx >> 2, h = idx & 3;
            int s = g_csrc[beg + i];
            float v = lrelu(__fadd_rn(g_alsrc[s * HH + h], g_aldst[n * HH + h]));
            exw[idx] = expf(__fsub_rn(v, g_m[n * HH + h]));
        }
    }
    __syncwarp();
    // Phase B: denominators + self-loop exp (lanes 0..3, head = lane)
    float d4 = 0.f, sx4 = 0.f;
    if (lane < 4) {
        int h = lane;
        float m = g_m[n * HH + h], ad = g_aldst[n * HH + h];
        float acc = 0.f;
        for (int i = 0; i < deg; i++) {
            float ex = cached ? exw[i * 4 + h]
                : expf(__fsub_rn(lrelu(__fadd_rn(g_alsrc[g_csrc[beg + i] * HH + h], ad)), m));
            acc = __fadd_rn(acc, ex);
        }
        sx4 = expf(__fsub_rn(lrelu(__fadd_rn(g_alsrc[n * HH + h], ad)), m));
        acc = __fadd_rn(acc, sx4);
        d4 = acc;
    }
    int head = lane >> 3;
    float den = __shfl_sync(0xffffffffu, d4, head);
    float sex = __shfl_sync(0xffffffffu, sx4, head);
    // Phase C: aggregation, lane owns 8 channels, ascending edges, self LAST
    int c0 = lane * 8;
    float m = g_m[n * HH + head], ad = g_aldst[n * HH + head];
    float acc[8] = {};
    for (int i = 0; i < deg; i++) {
        int s = g_csrc[beg + i];
        float ex = cached ? exw[i * 4 + head]
            : expf(__fsub_rn(lrelu(__fadd_rn(g_alsrc[s * HH + head], ad)), m));
        float a = __fdiv_rn(ex, den);
        const float4* hr = (const float4*)(g_h + (size_t)s * HD + c0);
        float4 h0 = hr[0], h1 = hr[1];
        acc[0] = __fadd_rn(acc[0], __fmul_rn(a, h0.x));
        acc[1] = __fadd_rn(acc[1], __fmul_rn(a, h0.y));
        acc[2] = __fadd_rn(acc[2], __fmul_rn(a, h0.z));
        acc[3] = __fadd_rn(acc[3], __fmul_rn(a, h0.w));
        acc[4] = __fadd_rn(acc[4], __fmul_rn(a, h1.x));
        acc[5] = __fadd_rn(acc[5], __fmul_rn(a, h1.y));
        acc[6] = __fadd_rn(acc[6], __fmul_rn(a, h1.z));
        acc[7] = __fadd_rn(acc[7], __fmul_rn(a, h1.w));
    }
    {
        float a = __fdiv_rn(sex, den);
        const float4* hr = (const float4*)(g_h + (size_t)n * HD + c0);
        float4 h0 = hr[0], h1 = hr[1];
        acc[0] = __fadd_rn(acc[0], __fmul_rn(a, h0.x));
        acc[1] = __fadd_rn(acc[1], __fmul_rn(a, h0.y));
        acc[2] = __fadd_rn(acc[2], __fmul_rn(a, h0.z));
        acc[3] = __fadd_rn(acc[3], __fmul_rn(a, h0.w));
        acc[4] = __fadd_rn(acc[4], __fmul_rn(a, h1.x));
        acc[5] = __fadd_rn(acc[5], __fmul_rn(a, h1.y));
        acc[6] = __fadd_rn(acc[6], __fmul_rn(a, h1.z));
        acc[7] = __fadd_rn(acc[7], __fmul_rn(a, h1.w));
    }
    float4 o0, o1;
    o0.x = __fadd_rn(acc[0], bgat[c0 + 0]);
    o0.y = __fadd_rn(acc[1], bgat[c0 + 1]);
    o0.z = __fadd_rn(acc[2], bgat[c0 + 2]);
    o0.w = __fadd_rn(acc[3], bgat[c0 + 3]);
    o1.x = __fadd_rn(acc[4], bgat[c0 + 4]);
    o1.y = __fadd_rn(acc[5], bgat[c0 + 5]);
    o1.z = __fadd_rn(acc[6], bgat[c0 + 6]);
    o1.w = __fadd_rn(acc[7], bgat[c0 + 7]);
    float4* op = (float4*)(g_xg + (size_t)n * HD + c0);
    op[0] = o0; op[1] = o1;
}

// score: vec2 adjacent-pair + shfl tree; div.rn; tanhf.
__global__ void score_kernel(const float* __restrict__ p) {
    int n = (blockIdx.x * blockDim.x + threadIdx.x) >> 5;
    int lane = threadIdx.x & 31;
    if (n >= NN) return;
    const float* xr = g_xl + (size_t)n * HIDC;
    int c = lane * 2;
    float z = __fmul_rn(xr[c], p[c]);
    z = __fadd_rn(z, __fmul_rn(xr[c + 1], p[c + 1]));
    float q = __fmul_rn(p[c], p[c]);
    q = __fadd_rn(q, __fmul_rn(p[c + 1], p[c + 1]));
#pragma unroll
    for (int off = 16; off > 0; off >>= 1) {
        z = __fadd_rn(z, __shfl_down_sync(0xffffffffu, z, off));
        q = __fadd_rn(q, __shfl_down_sync(0xffffffffu, q, off));
    }
    if (lane == 0) g_score[n] = tanhf(__fdiv_rn(z, sqrtf(q)));
}

// per-graph bitonic sort of 1024 (score desc, index asc); take top 512
__global__ void topk_kernel() {
    __shared__ float sv[1024];
    __shared__ int   si[1024];
    int b = blockIdx.x, t = threadIdx.x;
    sv[t] = g_score[b * NPG + t];
    si[t] = t;
    __syncthreads();
    for (int k = 2; k <= 1024; k <<= 1) {
        for (int j = k >> 1; j > 0; j >>= 1) {
            int ixj = t ^ j;
            if (ixj > t) {
                float v1 = sv[t], v2 = sv[ixj];
                int   i1 = si[t], i2 = si[ixj];
                bool before = (v1 > v2) || (v1 == v2 && i1 < i2);
                bool keep = ((t & k) == 0) ? before : !before;
                if (!keep) { sv[t] = v2; sv[ixj] = v1; si[t] = i2; si[ixj] = i1; }
            }
            __syncthreads();
        }
    }
    if (t < KK) {
        int gi = b * NPG + si[t];
        g_perm[b * KK + t] = gi;
        g_topv[b * KK + t] = sv[t];
        g_nmap[gi] = b * KK + t;
    }
}

__global__ void xp_kernel(float* __restrict__ out) {
    int idx = blockIdx.x * blockDim.x + threadIdx.x;
    if (idx >= BB * KK * HIDC) return;
    int r = idx >> 6, c = idx & 63;
    int node = g_perm[r];
    out[OFF_XP + idx] = __fmul_rn(g_xl[(size_t)node * HIDC + c], g_topv[r]);
    if (c == 0) out[OFF_BO + r] = (float)(r >> 9);
}

__global__ void edgeout_kernel(const int* __restrict__ ei,
                               const float* __restrict__ edge, float* __restrict__ out) {
    int e = blockIdx.x * blockDim.x + threadIdx.x;
    if (e >= EE) return;
    int s = ei[e], d = ei[EE + e];
    bool inb = ((unsigned)s < NN) && ((unsigned)d < NN);
    int ns = inb ? g_nmap[s] : -1;
    int nd = inb ? g_nmap[d] : -1;
    bool val = (ns >= 0) && (nd >= 0);
    out[OFF_EI + e]      = val ? (float)ns : -1.0f;
    out[OFF_EI + EE + e] = val ? (float)nd : -1.0f;
    const float4* ep = (const float4*)(edge + (size_t)e * 8);
    float4 a = ep[0], b2 = ep[1];
    if (!val) { a = make_float4(0.f, 0.f, 0.f, 0.f); b2 = a; }
    float4* op = (float4*)(out + OFF_EN + (size_t)e * 8);
    op[0] = a; op[1] = b2;
}

// x1: thread per (graph, channel); sequential r, div.rn for mean
__global__ void x1_kernel(float* __restrict__ out) {
    int idx = blockIdx.x * blockDim.x + threadIdx.x;   // BB*HIDC
    if (idx >= BB * HIDC) return;
    int b = idx >> 6, c = idx & 63;
    const float* xp = out + OFF_XP + (size_t)b * KK * HIDC;
    float sum = 0.f, mx = -INFINITY;
    for (int r = 0; r < KK; r++) {
        float v = xp[(size_t)r * HIDC + c];
        sum = __fadd_rn(sum, v);
        mx = fmaxf(mx, v);
    }
    out[OFF_X1 + b * 128 + c]      = __fdiv_rn(sum, 512.0f);
    out[OFF_X1 + b * 128 + 64 + c] = mx;
}

// ---------------- launcher ----------------
extern "C" void kernel_launch(void* const* d_in, const int* in_sizes, int n_in,
                              void* d_out, int out_size) {
    const float* x     = (const float*)d_in[0];
    const int*   ei    = (const int*)d_in[1];
    const float* edge  = (const float*)d_in[2];
    const float* W     = (const float*)d_in[4];
    const float* a_src = (const float*)d_in[5];
    const float* a_dst = (const float*)d_in[6];
    const float* b_gat = (const float*)d_in[7];
    const float* W_lin = (const float*)d_in[8];
    const float* b_lin = (const float*)d_in[9];
    const float* p_pool= (const float*)d_in[10];
    float* out = (float*)d_out;

    float *p_h = nullptr, *p_xg = nullptr, *p_xl = nullptr;
    cudaGetSymbolAddress((void**)&p_h,  g_h);
    cudaGetSymbolAddress((void**)&p_xg, g_xg);
    cudaGetSymbolAddress((void**)&p_xl, g_xl);

    init_kernel<<<NN / 256, 256>>>();

    dim3 g1(HD / 128, NN / 128);           // (2, 256)
    gemm_tiled<128, 128, 8, 8><<<g1, 256>>>(x, W, nullptr, p_h, INC, HD);

    al_kernel<<<NN * HH * 32 / 256, 256>>>(a_src, a_dst);
    edge_max_kernel<<<EE / 256, 256>>>(ei);
    scan_kernel<<<1, 1024>>>();
    scatter_kernel<<<EE / 256, 256>>>(ei);
    sortcsr_kernel<<<NN / 256, 256>>>(ei);
    softagg_kernel<<<NN * 32 / 256, 256>>>(b_gat);

    dim3 g2(HIDC / 64, NN / 128);          // (1, 256)
    gemm_tiled<128, 64, 8, 4><<<g2, 256>>>(p_xg, W_lin, b_lin, p_xl, HD, HIDC);

    score_kernel<<<NN * 32 / 256, 256>>>(p_pool);
    topk_kernel<<<BB, 1024>>>();
    xp_kernel<<<BB * KK * HIDC / 256, 256>>>(out);
    edgeout_kernel<<<EE / 256, 256>>>(ei, edge, out);
    x1_kernel<<<BB * HIDC / 256, 256>>>(out);
}